// round 16
// baseline (speedup 1.0000x reference)
#include <cuda_runtime.h>
#include <cuda_bf16.h>
#include <stdint.h>

#define NE 8
#define D 512
#define MAXT 65536

// ---- tcgen05 availability: only in the arch-specific (sm_103a/sm_100a) pass
#if defined(__CUDA_ARCH__) && (defined(__CUDA_ARCH_FEAT_SM103_ALL) || \
    defined(__CUDA_ARCH_FEAT_SM100_ALL) || \
    (defined(__CUDA_ARCH_SPECIFIC__) && (__CUDA_ARCH_SPECIFIC__ >= 1000)))
#define TC_OK 1
#else
#define TC_OK 0
#endif

#define BM 128
#define BN 256         // per-CTA N (grid.y = 2 covers D=512)
#define BK 32          // fp32 elements per k-chunk
#define NCHUNK (D / BK)
#define NTH 544        // warps 0-15: compute; warp 16: B producer

// ---------------- scratch ---------------------------------------------------
__device__ int g_cnt[NE];
__device__ int g_off[NE + 1];
__device__ int g_cur[NE];
__device__ int g_idx[MAXT];
// Pre-converted W: per (expert, chunk, nh): 32KB = [hi 16KB][lo 16KB],
// each the exact SW64-swizzled [n=256][k=32] bf16 SMEM tile image.
__device__ unsigned char g_Wimg[(size_t)NE * NCHUNK * 2 * 32768];

// ---------------- PTX helpers ----------------------------------------------
__device__ __forceinline__ uint32_t smem_u32(const void* p) {
    uint32_t a;
    asm("{ .reg .u64 t; cvta.to.shared.u64 t, %1; cvt.u32.u64 %0, t; }"
        : "=r"(a) : "l"(p));
    return a;
}
#if TC_OK
__device__ __forceinline__ uint32_t elect_one() {
    uint32_t p;
    asm volatile("{\n\t.reg .pred p;\n\telect.sync _|p, 0xFFFFFFFF;\n\t"
                 "selp.b32 %0, 1, 0, p;\n\t}" : "=r"(p));
    return p;
}
__device__ __forceinline__ void mbar_init(uint32_t mbar, uint32_t cnt) {
    asm volatile("mbarrier.init.shared.b64 [%0], %1;" :: "r"(mbar), "r"(cnt)
                 : "memory");
}
__device__ __forceinline__ void mbar_wait(uint32_t mbar, uint32_t parity) {
    asm volatile(
        "{\n\t.reg .pred P;\n\t"
        "WL_%=:\n\t"
        "mbarrier.try_wait.parity.acquire.cta.shared::cta.b64 P, [%0], %1, 0x989680;\n\t"
        "@!P bra WL_%=;\n\t}"
        :: "r"(mbar), "r"(parity) : "memory");
}
__device__ __forceinline__ void mbar_arrive_tx(uint32_t mbar, uint32_t bytes) {
    asm volatile("mbarrier.arrive.expect_tx.shared.b64 _, [%0], %1;"
                 :: "r"(mbar), "r"(bytes) : "memory");
}
__device__ __forceinline__ void bulk_g2s(uint32_t dst, const void* src,
                                         uint32_t bytes, uint32_t mbar) {
    asm volatile(
        "cp.async.bulk.shared::cta.global.mbarrier::complete_tx::bytes "
        "[%0], [%1], %2, [%3];"
        :: "r"(dst), "l"(src), "r"(bytes), "r"(mbar) : "memory");
}
__device__ __forceinline__ void tmem_alloc(uint32_t smem_dst, uint32_t ncols) {
    asm volatile("tcgen05.alloc.cta_group::1.sync.aligned.shared::cta.b32 [%0], %1;"
                 :: "r"(smem_dst), "r"(ncols) : "memory");
}
__device__ __forceinline__ void tmem_dealloc(uint32_t tmem, uint32_t ncols) {
    asm volatile("tcgen05.dealloc.cta_group::1.sync.aligned.b32 %0, %1;"
                 :: "r"(tmem), "r"(ncols));
}
__device__ __forceinline__ void tmem_relinquish() {
    asm volatile("tcgen05.relinquish_alloc_permit.cta_group::1.sync.aligned;");
}
__device__ __forceinline__ void mma_f16_ss(uint32_t d, uint64_t a, uint64_t b,
                                           uint32_t idesc, uint32_t en) {
    asm volatile(
        "{\n\t.reg .pred p;\n\t"
        "setp.ne.u32 p, %5, 0;\n\t"
        "tcgen05.mma.cta_group::1.kind::f16 [%0], %1, %2, %3, {%4, %4, %4, %4}, p;\n\t}"
        :: "r"(d), "l"(a), "l"(b), "r"(idesc), "r"(0u), "r"(en) : "memory");
}
__device__ __forceinline__ void tc_commit(uint32_t mbar) {
    asm volatile(
        "tcgen05.commit.cta_group::1.mbarrier::arrive::one.shared::cluster.b64 [%0];"
        :: "r"(mbar) : "memory");
}
__device__ __forceinline__ void fence_async_smem() {
    asm volatile("fence.proxy.async.shared::cta;" ::: "memory");
}
__device__ __forceinline__ void tc_fence_after() {
    asm volatile("tcgen05.fence::after_thread_sync;" ::: "memory");
}
__device__ __forceinline__ void ldtm_x32(uint32_t* r, uint32_t addr) {
    asm volatile(
        "tcgen05.ld.sync.aligned.32x32b.x32.b32 "
        "{%0, %1, %2, %3, %4, %5, %6, %7, %8, %9, %10, %11, %12, %13, %14, %15, "
        "%16, %17, %18, %19, %20, %21, %22, %23, %24, %25, %26, %27, %28, %29, %30, %31}, [%32];"
        : "=r"(r[0]), "=r"(r[1]), "=r"(r[2]), "=r"(r[3]), "=r"(r[4]), "=r"(r[5]),
          "=r"(r[6]), "=r"(r[7]), "=r"(r[8]), "=r"(r[9]), "=r"(r[10]), "=r"(r[11]),
          "=r"(r[12]), "=r"(r[13]), "=r"(r[14]), "=r"(r[15]), "=r"(r[16]), "=r"(r[17]),
          "=r"(r[18]), "=r"(r[19]), "=r"(r[20]), "=r"(r[21]), "=r"(r[22]), "=r"(r[23]),
          "=r"(r[24]), "=r"(r[25]), "=r"(r[26]), "=r"(r[27]), "=r"(r[28]), "=r"(r[29]),
          "=r"(r[30]), "=r"(r[31])
        : "r"(addr));
}
__device__ __forceinline__ void tmem_wait_ld() {
    asm volatile("tcgen05.wait::ld.sync.aligned;" ::: "memory");
}
// SW64 K-major descriptor: 64B rows, 8-row atom (512B). LBO=1, SBO=32.
__device__ __forceinline__ uint64_t sw64_desc(uint32_t addr) {
    uint64_t d = (uint64_t)((addr >> 4) & 0x3FFFu);
    d |= (uint64_t)1 << 16;    // LBO = 1  (16B)
    d |= (uint64_t)32 << 32;   // SBO = 32 (512B = 8 rows x 64B)
    d |= (uint64_t)1 << 46;    // version = 1 (Blackwell)
    d |= (uint64_t)4 << 61;    // layout = SW64
    return d;
}
#endif // TC_OK

#define SWZ64(o) ((o) ^ ((((uint32_t)(o)) >> 3) & 0x30u))

// bf16 hi/lo split of a pair of adjacent fp32 values, packed as bf16x2.
__device__ __forceinline__ void split2(float f0, float f1, uint32_t& hi, uint32_t& lo) {
    asm("cvt.rn.bf16x2.f32 %0, %1, %2;" : "=r"(hi) : "f"(f1), "f"(f0));
    float h0 = __uint_as_float(hi << 16);
    float h1 = __uint_as_float(hi & 0xFFFF0000u);
    float r0 = f0 - h0;
    float r1 = f1 - h1;
    asm("cvt.rn.bf16x2.f32 %0, %1, %2;" : "=r"(lo) : "f"(r1), "f"(r0));
}

// idesc kind::f16: F32 acc, BF16 a/b (K-major), N=128, M=128
#define IDESC128 0x8200490u

// SMEM layout (dynamic) — 100KB total -> 2 CTAs / SM
#define SM_MBE   0                     // 4 x 8B: empty (commit target) per B sub-stage
#define SM_MBF   32                    // 4 x 8B: B sub-stage tx barriers
#define SM_TP    64
#define SM_BIAS  128                   // 256 floats (1KB)
#define SM_TOK   1152                  // 128 ints
#define SM_A     4096                  // 2 buffers x 16KB (hi 8KB + lo 8KB)
#define SM_B     36864                 // 4 sub-stages x 16KB (hi 8KB + lo 8KB)
#define SM_TOTAL 102400

// ---------------- pre-passes ------------------------------------------------
__global__ void k_zero() {
    if (threadIdx.x < NE) g_cnt[threadIdx.x] = 0;
}
__global__ void k_count(const int* __restrict__ z, int T,
                        float* __restrict__ pre, int has_pre) {
    __shared__ int h[NE];
    if (threadIdx.x < NE) h[threadIdx.x] = 0;
    __syncthreads();
    for (int i = blockIdx.x * blockDim.x + threadIdx.x; i < T;
         i += gridDim.x * blockDim.x) {
        int e = z[i];
        atomicAdd(&h[e], 1);
        if (has_pre) pre[i] = (float)e;
    }
    __syncthreads();
    if (threadIdx.x < NE) atomicAdd(&g_cnt[threadIdx.x], h[threadIdx.x]);
}
__global__ void k_scan() {
    int s = 0;
    for (int e = 0; e < NE; e++) {
        g_off[e] = s;
        g_cur[e] = s;
        s += g_cnt[e];
    }
    g_off[NE] = s;
}
__global__ void k_scatter(const int* __restrict__ z, int T) {
    __shared__ int h[NE], base[NE];
    if (threadIdx.x < NE) h[threadIdx.x] = 0;
    __syncthreads();
    int i = blockIdx.x * blockDim.x + threadIdx.x;
    int e = -1;
    if (i < T) {
        e = z[i];
        atomicAdd(&h[e], 1);
    }
    __syncthreads();
    if (threadIdx.x < NE) {
        base[threadIdx.x] = atomicAdd(&g_cur[threadIdx.x], h[threadIdx.x]);
        h[threadIdx.x] = 0;
    }
    __syncthreads();
    if (i < T) {
        int r = atomicAdd(&h[e], 1);
        g_idx[base[e] + r] = i;
    }
}

// ---- one-time W conversion into swizzled SMEM tile images ------------------
// block = (expert, chunk). Output per (e,c,nh): 32KB = [hi 16KB][lo 16KB],
// SW64-swizzled [n=256][k=32] bf16 (n-major rows of 64B).
__global__ void k_convW(const float* __restrict__ W) {
    int blk = blockIdx.x;
    int e = blk >> 4;
    int c = blk & 15;
    int k0 = c * BK;
    int tid = threadIdx.x;
    int kq = tid >> 6;              // 0..3 -> k rows kq*8..+8
    int nq = tid & 63;              // n groups of 8
    const float* Wb = W + (size_t)e * D * D;
#pragma unroll
    for (int nn = 0; nn < 8; nn++) {
        int n = nq * 8 + nn;
        int nh = n >> 8;
        int nl = n & 255;
        float w[8];
#pragma unroll
        for (int kk = 0; kk < 8; kk++)
            w[kk] = Wb[(size_t)(k0 + kq * 8 + kk) * D + n];
        uint32_t hv[4], lv[4];
#pragma unroll
        for (int kp = 0; kp < 4; kp++)
            split2(w[2 * kp], w[2 * kp + 1], hv[kp], lv[kp]);
        unsigned char* base = g_Wimg + ((size_t)blk * 2 + nh) * 32768;
        uint32_t off = SWZ64((uint32_t)(nl * 64 + kq * 16));
        *(uint4*)(base + off) = make_uint4(hv[0], hv[1], hv[2], hv[3]);
        *(uint4*)(base + 16384 + off) = make_uint4(lv[0], lv[1], lv[2], lv[3]);
    }
}

// -- tcgen05 GEMM: occ-2, A depth-2, B as 4 x N=128 sub-stages (2-chunk lead)
__global__ __launch_bounds__(NTH, 2)
void k_gemm_tc(const float* __restrict__ x, const float* __restrict__ bias_g,
               float* __restrict__ y) {
#if TC_OK
    extern __shared__ char smem[];
    const uint32_t sb = smem_u32(smem);
    float* bias_s = (float*)(smem + SM_BIAS);
    int* tok_s = (int*)(smem + SM_TOK);

    // ---- map blockIdx.x -> (expert, row offset) ----
    int tile = blockIdx.x;
    int e = -1, m0 = 0, cnt = 0;
    {
        int t0 = 0;
#pragma unroll
        for (int q = 0; q < NE; q++) {
            int c = g_off[q + 1] - g_off[q];
            int nt = (c + BM - 1) / BM;
            if (e < 0 && tile < t0 + nt) {
                e = q;
                m0 = (tile - t0) * BM;
                cnt = c;
            }
            t0 += nt;
        }
    }
    if (e < 0) return;
    const int seg = g_off[e];
    const int nh = blockIdx.y;            // N-half 0/1
    const int n0 = nh * BN;

    const int tid = threadIdx.x;
    const int wid = tid >> 5;
    const int lane = tid & 31;

    if (tid < BN) bias_s[tid] = bias_g[(size_t)e * D + n0 + tid];
    if (tid < BM) {
        int r = m0 + tid;
        tok_s[tid] = (r < cnt) ? g_idx[seg + r] : -1;
    }
    if (wid == 0) {
        tmem_alloc(sb + SM_TP, 256);
        tmem_relinquish();
    }
    if (tid == 0) {
#pragma unroll
        for (int s = 0; s < 4; s++) {
            mbar_init(sb + SM_MBE + s * 8, 1);
            mbar_init(sb + SM_MBF + s * 8, 1);
        }
    }
    __syncthreads();
    uint32_t tmem;
    asm volatile("ld.shared.b32 %0, [%1];" : "=r"(tmem) : "r"(sb + SM_TP));

    const unsigned char* wsrc0 =
        g_Wimg + ((size_t)e * NCHUNK * 2 + nh) * 32768;

    if (wid == 16) {
        // ---- B producer: 32 sub-uses (2 per chunk), up to 4 sub-uses ahead -
        if (elect_one()) {
            for (int u = 0; u < 2 * NCHUNK; u++) {
                const int s = u & 3;
                if (u >= 4)
                    mbar_wait(sb + SM_MBE + s * 8, (((u >> 2) & 1) ^ 1));
                const uint32_t mbF = sb + SM_MBF + s * 8;
                const int c = u >> 1;
                const int h = u & 1;
                const unsigned char* src = wsrc0 + (size_t)c * 65536;
                mbar_arrive_tx(mbF, 16384);
                bulk_g2s(sb + SM_B + s * 16384, src + h * 8192, 8192, mbF);
                bulk_g2s(sb + SM_B + s * 16384 + 8192,
                         src + 16384 + h * 8192, 8192, mbF);
            }
        }
    } else {
        // ---- compute warps 0-15: A conversion + MMA issue ------------------
        const int row0 = tid >> 3;
        const int row1 = (tid + 512) >> 3;
        const int c4 = tid & 7;
        const int tk0 = tok_s[row0];
        const int tk1 = tok_s[row1];
        const float* p0 = (tk0 >= 0) ? x + (size_t)tk0 * D + c4 * 4 : 0;
        const float* p1 = (tk1 >= 0) ? x + (size_t)tk1 * D + c4 * 4 : 0;
        const uint32_t offA0 = SWZ64((uint32_t)(row0 * 64 + c4 * 8));
        const uint32_t offA1 = SWZ64((uint32_t)(row1 * 64 + c4 * 8));

        float4 v0, v1;
        const float4 fz = make_float4(0.f, 0.f, 0.f, 0.f);
        v0 = p0 ? *(const float4*)(p0) : fz;
        v1 = p1 ? *(const float4*)(p1) : fz;

        for (int c = 0; c < NCHUNK; c++) {
            const int sA = c & 1;

            // A stage reuse: wait for the h=1 commit of chunk c-2
            if (c >= 2) {
                const int up = 2 * (c - 2) + 1;
                mbar_wait(sb + SM_MBE + (up & 3) * 8, (up >> 2) & 1);
            }

            // A: split prefetched regs -> hi/lo bf16, SW64
            char* Ah = smem + SM_A + sA * 16384;
            char* Al = Ah + 8192;
            {
                uint32_t h0, l0, h1, l1;
                split2(v0.x, v0.y, h0, l0);
                split2(v0.z, v0.w, h1, l1);
                *(uint2*)(Ah + offA0) = make_uint2(h0, h1);
                *(uint2*)(Al + offA0) = make_uint2(l0, l1);
                split2(v1.x, v1.y, h0, l0);
                split2(v1.z, v1.w, h1, l1);
                *(uint2*)(Ah + offA1) = make_uint2(h0, h1);
                *(uint2*)(Al + offA1) = make_uint2(l0, l1);
            }

            // prefetch next chunk's A (issues before any blocking)
            if (c + 1 < NCHUNK) {
                int k0n = (c + 1) * BK;
                v0 = p0 ? *(const float4*)(p0 + k0n) : fz;
                v1 = p1 ? *(const float4*)(p1 + k0n) : fz;
            }

            fence_async_smem();
            // full named barrier over the 512 compute threads
            asm volatile("bar.sync 1, 512;" ::: "memory");

            if (wid == 0) {
                if (elect_one()) {
                    uint64_t aH = sw64_desc(sb + SM_A + sA * 16384);
                    uint64_t aL = aH + 512;          // +8192B in 16B units
#pragma unroll
                    for (int h = 0; h < 2; h++) {
                        const int u = 2 * c + h;
                        const int s = u & 3;
                        mbar_wait(sb + SM_MBF + s * 8, (u >> 2) & 1);
                        uint64_t bH = sw64_desc(sb + SM_B + s * 16384);
                        uint64_t bL = bH + 512;      // +8192B
                        uint32_t dt = tmem + h * 128;
#pragma unroll
                        for (int ks = 0; ks < 2; ks++) {
                            uint64_t dk = ks * 2;    // +32B per K=16 step
                            uint32_t first = (c == 0 && ks == 0) ? 0u : 1u;
                            mma_f16_ss(dt, aH + dk, bH + dk, IDESC128, first);
                            mma_f16_ss(dt, aH + dk, bL + dk, IDESC128, 1u);
                            mma_f16_ss(dt, aL + dk, bH + dk, IDESC128, 1u);
                        }
                        tc_commit(sb + SM_MBE + s * 8);
                    }
                }
            }
        }

        // ---- drain: each sub-stage's 8th completion is parity 1 ----
        mbar_wait(sb + SM_MBE + 0, 1);
        mbar_wait(sb + SM_MBE + 8, 1);
        mbar_wait(sb + SM_MBE + 16, 1);
        mbar_wait(sb + SM_MBE + 24, 1);
        tc_fence_after();

        // ---- epilogue: 16 warps, each 32 rows x 64 cols ----
        const int g = wid & 3;                // row group
        const int h = wid >> 2;               // col quarter (0..3)
        const int row = g * 32 + lane;
        const int tk = tok_s[row];
        const int cb = h * 64;
        const uint32_t dbase = tmem + cb;
        float* dst = (tk >= 0) ? (y + (size_t)tk * D + n0 + cb) : 0;

#pragma unroll
        for (int i = 0; i < 2; i++) {
            uint32_t r[32];
            ldtm_x32(r, dbase + i * 32);
            tmem_wait_ld();
            if (tk >= 0) {
#pragma unroll
                for (int cc = 0; cc < 32; cc += 4) {
                    float4 o;
                    o.x = __uint_as_float(r[cc + 0]) + bias_s[cb + i * 32 + cc + 0];
                    o.y = __uint_as_float(r[cc + 1]) + bias_s[cb + i * 32 + cc + 1];
                    o.z = __uint_as_float(r[cc + 2]) + bias_s[cb + i * 32 + cc + 2];
                    o.w = __uint_as_float(r[cc + 3]) + bias_s[cb + i * 32 + cc + 3];
                    *(float4*)(dst + i * 32 + cc) = o;
                }
            }
        }
    }

    __syncthreads();                          // all 17 warps re-join
    if (wid == 0) tmem_dealloc(tmem, 256);
#endif // TC_OK
}

// ---------------- fallback fp32 f32x2 GEMM (empty stub when TC_OK) ----------
#define FBM 128
#define FBN 128
#define FBK 16
#define FPAD 4

__global__ __launch_bounds__(256, 2)
void k_gemm_fb(const float* __restrict__ x, const float* __restrict__ W,
               const float* __restrict__ bias_g, float* __restrict__ y) {
#if !TC_OK
    __shared__ float As[FBK][FBM + FPAD];
    __shared__ float Bs[FBK][FBN + FPAD];
    __shared__ int tok[FBM];

    int tile = blockIdx.x;
    int e = -1, m0 = 0, cnt = 0;
    {
        int t0 = 0;
#pragma unroll
        for (int q = 0; q < NE; q++) {
            int c = g_off[q + 1] - g_off[q];
            int nt = (c + FBM - 1) / FBM;
            if (e < 0 && tile < t0 + nt) {
                e = q;
                m0 = (tile - t0) * FBM;
                cnt = c;
            }
            t0 += nt;
        }
    }
    if (e < 0) return;
    int seg = g_off[e];
    int n0 = blockIdx.y * FBN;

    int t = threadIdx.x;
    int ty = t >> 4;
    int tx = t & 15;

    if (t < FBM) {
        int r = m0 + t;
        tok[t] = (r < cnt) ? g_idx[seg + r] : -1;
    }
    __syncthreads();

    const float* Wbase = W + (size_t)e * D * D;

    unsigned long long acc[8][4];
#pragma unroll
    for (int i = 0; i < 8; i++)
#pragma unroll
        for (int j = 0; j < 4; j++) acc[i][j] = 0ULL;

    for (int kt = 0; kt < D / FBK; kt++) {
        int k0 = kt * FBK;
#pragma unroll
        for (int l = 0; l < 2; l++) {
            int i = t + l * 256;
            int row = i >> 2;
            int c4 = i & 3;
            int tk = tok[row];
            float4 v = make_float4(0.f, 0.f, 0.f, 0.f);
            if (tk >= 0)
                v = *(const float4*)(x + (size_t)tk * D + k0 + c4 * 4);
            As[c4 * 4 + 0][row] = v.x;
            As[c4 * 4 + 1][row] = v.y;
            As[c4 * 4 + 2][row] = v.z;
            As[c4 * 4 + 3][row] = v.w;
        }
#pragma unroll
        for (int l = 0; l < 2; l++) {
            int i = t + l * 256;
            int row = i >> 5;
            int c4 = i & 31;
            float4 v = *(const float4*)(Wbase + (size_t)(k0 + row) * D + n0 + c4 * 4);
            *(float4*)&Bs[row][c4 * 4] = v;
        }
        __syncthreads();

#pragma unroll
        for (int k = 0; k < FBK; k++) {
            float a[8], bb[8];
            {
                float4 a0 = *(const float4*)&As[k][ty * 4];
                float4 a1 = *(const float4*)&As[k][64 + ty * 4];
                a[0] = a0.x; a[1] = a0.y; a[2] = a0.z; a[3] = a0.w;
                a[4] = a1.x; a[5] = a1.y; a[6] = a1.z; a[7] = a1.w;
                float4 b0 = *(const float4*)&Bs[k][tx * 4];
                float4 b1 = *(const float4*)&Bs[k][64 + tx * 4];
                bb[0] = b0.x; bb[1] = b0.y; bb[2] = b0.z; bb[3] = b0.w;
                bb[4] = b1.x; bb[5] = b1.y; bb[6] = b1.z; bb[7] = b1.w;
            }
            unsigned long long b2[4];
#pragma unroll
            for (int j = 0; j < 4; j++) {
                asm("mov.b64 %0, {%1, %2};"
                    : "=l"(b2[j])
                    : "r"(__float_as_uint(bb[2 * j])),
                      "r"(__float_as_uint(bb[2 * j + 1])));
            }
#pragma unroll
            for (int i = 0; i < 8; i++) {
                unsigned long long a2;
                asm("mov.b64 %0, {%1, %1};"
                    : "=l"(a2)
                    : "r"(__float_as_uint(a[i])));
#pragma unroll
                for (int j = 0; j < 4; j++) {
                    asm("fma.rn.f32x2 %0, %1, %2, %0;"
                        : "+l"(acc[i][j])
                        : "l"(a2), "l"(b2[j]));
                }
            }
        }
        __syncthreads();
    }

    float bv[8];
    {
        float4 q0 = *(const float4*)(bias_g + (size_t)e * D + n0 + tx * 4);
        float4 q1 = *(const float4*)(bias_g + (size_t)e * D + n0 + 64 + tx * 4);
        bv[0] = q0.x; bv[1] = q0.y; bv[2] = q0.z; bv[3] = q0.w;
        bv[4] = q1.x; bv[5] = q1.y; bv[6] = q1.z; bv[7] = q1.w;
    }
#pragma unroll
    for (int i = 0; i < 8; i++) {
        int row = (i < 4) ? (ty * 4 + i) : (64 + ty * 4 + (i - 4));
        int tk = tok[row];
        if (tk < 0) continue;
        float o[8];
#pragma unroll
        for (int j = 0; j < 4; j++) {
            unsigned r0, r1;
            asm("mov.b64 {%0, %1}, %2;"
                : "=r"(r0), "=r"(r1)
                : "l"(acc[i][j]));
            o[2 * j] = __uint_as_float(r0) + bv[2 * j];
            o[2 * j + 1] = __uint_as_float(r1) + bv[2 * j + 1];
        }
        float* dst = y + (size_t)tk * D + n0;
        *(float4*)(dst + tx * 4) = make_float4(o[0], o[1], o[2], o[3]);
        *(float4*)(dst + 64 + tx * 4) = make_float4(o[4], o[5], o[6], o[7]);
    }
#endif // !TC_OK
}

// ---------------------------------------------------------------------------
extern "C" void kernel_launch(void* const* d_in, const int* in_sizes, int n_in,
                              void* d_out, int out_size) {
    const int* z = (const int*)d_in[0];
    const float* x = (const float*)d_in[1];
    const float* W = (const float*)d_in[2];
    const float* b = (const float*)d_in[3];
    float* out = (float*)d_out;

    int T = in_sizes[0];
    if (T > MAXT) T = MAXT;
    long long y_elems = (long long)T * D;
    long long prefix = (long long)out_size - y_elems;
    if (prefix < 0) prefix = 0;
    float* y = out + prefix;

    k_zero<<<1, 32>>>();
    k_count<<<256, 256>>>(z, T, out, (prefix >= T) ? 1 : 0);
    k_scan<<<1, 1>>>();
    k_scatter<<<(T + 255) / 256, 256>>>(z, T);
    k_convW<<<NE * NCHUNK, 256>>>(W);

    // tcgen05 path (no-op stub if this cubin lacks the 'a' feature set)
    cudaFuncSetAttribute(k_gemm_tc, cudaFuncAttributeMaxDynamicSharedMemorySize,
                         SM_TOTAL);
    dim3 grid_tc((T + BM - 1) / BM + NE, 2);
    k_gemm_tc<<<grid_tc, NTH, SM_TOTAL>>>(x, b, y);

    // fp32 fallback (no-op stub when the tcgen05 path is compiled in)
    dim3 grid_fb((T + FBM - 1) / FBM + NE, D / FBN);
    k_gemm_fb<<<grid_fb, 256>>>(x, W, b, y);
}

// round 17
// speedup vs baseline: 1.0497x; 1.0497x over previous
#include <cuda_runtime.h>
#include <cuda_bf16.h>
#include <stdint.h>

#define NE 8
#define D 512
#define MAXT 65536

// ---- tcgen05 availability: only in the arch-specific (sm_103a/sm_100a) pass
#if defined(__CUDA_ARCH__) && (defined(__CUDA_ARCH_FEAT_SM103_ALL) || \
    defined(__CUDA_ARCH_FEAT_SM100_ALL) || \
    (defined(__CUDA_ARCH_SPECIFIC__) && (__CUDA_ARCH_SPECIFIC__ >= 1000)))
#define TC_OK 1
#else
#define TC_OK 0
#endif

#define BM 128
#define BN 256         // per-CTA N half; nh = blockIdx.x & 1 (pair-adjacent)
#define BK 32          // fp32 elements per k-chunk
#define NCHUNK (D / BK)
#define NTH 544        // warps 0-15: compute; warp 16: B producer

// ---------------- scratch ---------------------------------------------------
__device__ int g_cnt[NE];              // static-zero; re-zeroed by k_scan
__device__ int g_off[NE + 1];
__device__ int g_cur[NE];
__device__ int g_idx[MAXT];
// Pre-converted W: per (expert, chunk, nh): 32KB = [hi 16KB][lo 16KB],
// each the exact SW64-swizzled [n=256][k=32] bf16 SMEM tile image.
__device__ unsigned char g_Wimg[(size_t)NE * NCHUNK * 2 * 32768];

// ---------------- PTX helpers ----------------------------------------------
__device__ __forceinline__ uint32_t smem_u32(const void* p) {
    uint32_t a;
    asm("{ .reg .u64 t; cvta.to.shared.u64 t, %1; cvt.u32.u64 %0, t; }"
        : "=r"(a) : "l"(p));
    return a;
}
#if TC_OK
__device__ __forceinline__ uint32_t elect_one() {
    uint32_t p;
    asm volatile("{\n\t.reg .pred p;\n\telect.sync _|p, 0xFFFFFFFF;\n\t"
                 "selp.b32 %0, 1, 0, p;\n\t}" : "=r"(p));
    return p;
}
__device__ __forceinline__ void mbar_init(uint32_t mbar, uint32_t cnt) {
    asm volatile("mbarrier.init.shared.b64 [%0], %1;" :: "r"(mbar), "r"(cnt)
                 : "memory");
}
__device__ __forceinline__ void mbar_wait(uint32_t mbar, uint32_t parity) {
    asm volatile(
        "{\n\t.reg .pred P;\n\t"
        "WL_%=:\n\t"
        "mbarrier.try_wait.parity.acquire.cta.shared::cta.b64 P, [%0], %1, 0x989680;\n\t"
        "@!P bra WL_%=;\n\t}"
        :: "r"(mbar), "r"(parity) : "memory");
}
__device__ __forceinline__ void mbar_arrive_tx(uint32_t mbar, uint32_t bytes) {
    asm volatile("mbarrier.arrive.expect_tx.shared.b64 _, [%0], %1;"
                 :: "r"(mbar), "r"(bytes) : "memory");
}
__device__ __forceinline__ void bulk_g2s(uint32_t dst, const void* src,
                                         uint32_t bytes, uint32_t mbar) {
    asm volatile(
        "cp.async.bulk.shared::cta.global.mbarrier::complete_tx::bytes "
        "[%0], [%1], %2, [%3];"
        :: "r"(dst), "l"(src), "r"(bytes), "r"(mbar) : "memory");
}
__device__ __forceinline__ void tmem_alloc(uint32_t smem_dst, uint32_t ncols) {
    asm volatile("tcgen05.alloc.cta_group::1.sync.aligned.shared::cta.b32 [%0], %1;"
                 :: "r"(smem_dst), "r"(ncols) : "memory");
}
__device__ __forceinline__ void tmem_dealloc(uint32_t tmem, uint32_t ncols) {
    asm volatile("tcgen05.dealloc.cta_group::1.sync.aligned.b32 %0, %1;"
                 :: "r"(tmem), "r"(ncols));
}
__device__ __forceinline__ void tmem_relinquish() {
    asm volatile("tcgen05.relinquish_alloc_permit.cta_group::1.sync.aligned;");
}
__device__ __forceinline__ void mma_f16_ss(uint32_t d, uint64_t a, uint64_t b,
                                           uint32_t idesc, uint32_t en) {
    asm volatile(
        "{\n\t.reg .pred p;\n\t"
        "setp.ne.u32 p, %5, 0;\n\t"
        "tcgen05.mma.cta_group::1.kind::f16 [%0], %1, %2, %3, {%4, %4, %4, %4}, p;\n\t}"
        :: "r"(d), "l"(a), "l"(b), "r"(idesc), "r"(0u), "r"(en) : "memory");
}
__device__ __forceinline__ void tc_commit(uint32_t mbar) {
    asm volatile(
        "tcgen05.commit.cta_group::1.mbarrier::arrive::one.shared::cluster.b64 [%0];"
        :: "r"(mbar) : "memory");
}
__device__ __forceinline__ void fence_async_smem() {
    asm volatile("fence.proxy.async.shared::cta;" ::: "memory");
}
__device__ __forceinline__ void tc_fence_after() {
    asm volatile("tcgen05.fence::after_thread_sync;" ::: "memory");
}
__device__ __forceinline__ void ldtm_x32(uint32_t* r, uint32_t addr) {
    asm volatile(
        "tcgen05.ld.sync.aligned.32x32b.x32.b32 "
        "{%0, %1, %2, %3, %4, %5, %6, %7, %8, %9, %10, %11, %12, %13, %14, %15, "
        "%16, %17, %18, %19, %20, %21, %22, %23, %24, %25, %26, %27, %28, %29, %30, %31}, [%32];"
        : "=r"(r[0]), "=r"(r[1]), "=r"(r[2]), "=r"(r[3]), "=r"(r[4]), "=r"(r[5]),
          "=r"(r[6]), "=r"(r[7]), "=r"(r[8]), "=r"(r[9]), "=r"(r[10]), "=r"(r[11]),
          "=r"(r[12]), "=r"(r[13]), "=r"(r[14]), "=r"(r[15]), "=r"(r[16]), "=r"(r[17]),
          "=r"(r[18]), "=r"(r[19]), "=r"(r[20]), "=r"(r[21]), "=r"(r[22]), "=r"(r[23]),
          "=r"(r[24]), "=r"(r[25]), "=r"(r[26]), "=r"(r[27]), "=r"(r[28]), "=r"(r[29]),
          "=r"(r[30]), "=r"(r[31])
        : "r"(addr));
}
__device__ __forceinline__ void tmem_wait_ld() {
    asm volatile("tcgen05.wait::ld.sync.aligned;" ::: "memory");
}
// SW64 K-major descriptor: 64B rows, 8-row atom (512B). LBO=1, SBO=32.
__device__ __forceinline__ uint64_t sw64_desc(uint32_t addr) {
    uint64_t d = (uint64_t)((addr >> 4) & 0x3FFFu);
    d |= (uint64_t)1 << 16;    // LBO = 1  (16B)
    d |= (uint64_t)32 << 32;   // SBO = 32 (512B = 8 rows x 64B)
    d |= (uint64_t)1 << 46;    // version = 1 (Blackwell)
    d |= (uint64_t)4 << 61;    // layout = SW64
    return d;
}
#endif // TC_OK

#define SWZ64(o) ((o) ^ ((((uint32_t)(o)) >> 3) & 0x30u))

// bf16 hi/lo split of a pair of adjacent fp32 values, packed as bf16x2.
__device__ __forceinline__ void split2(float f0, float f1, uint32_t& hi, uint32_t& lo) {
    asm("cvt.rn.bf16x2.f32 %0, %1, %2;" : "=r"(hi) : "f"(f1), "f"(f0));
    float h0 = __uint_as_float(hi << 16);
    float h1 = __uint_as_float(hi & 0xFFFF0000u);
    float r0 = f0 - h0;
    float r1 = f1 - h1;
    asm("cvt.rn.bf16x2.f32 %0, %1, %2;" : "=r"(lo) : "f"(r1), "f"(r0));
}

// idesc kind::f16: F32 acc, BF16 a/b (K-major), N=256, M=128
#define IDESC 0x8400490u

// SMEM layout (dynamic) — 100KB total -> 2 CTAs / SM
#define SM_MBE0  0                     // empty barriers (commit target)
#define SM_MBE1  8
#define SM_MBF0  16                    // B-tx barriers
#define SM_MBF1  24
#define SM_TP    32
#define SM_BIAS  64                    // 256 floats (1KB)
#define SM_TOK   1088                  // 128 ints
#define SM_A     4096                  // 2 buffers x (hi 8KB + lo 8KB) = 32KB
#define SM_B     36864                 // 2 buffers x (hi 16KB + lo 16KB) = 64KB
#define SM_TOTAL 102400

// ---------------- pre-passes ------------------------------------------------
__global__ void k_count(const int* __restrict__ z, int T,
                        float* __restrict__ pre, int has_pre) {
    __shared__ int h[NE];
    if (threadIdx.x < NE) h[threadIdx.x] = 0;
    __syncthreads();
    for (int i = blockIdx.x * blockDim.x + threadIdx.x; i < T;
         i += gridDim.x * blockDim.x) {
        int e = z[i];
        atomicAdd(&h[e], 1);
        if (has_pre) pre[i] = (float)e;
    }
    __syncthreads();
    if (threadIdx.x < NE) atomicAdd(&g_cnt[threadIdx.x], h[threadIdx.x]);
}
__global__ void k_scan() {
    int s = 0;
    for (int e = 0; e < NE; e++) {
        g_off[e] = s;
        g_cur[e] = s;
        s += g_cnt[e];
        g_cnt[e] = 0;            // reset for the next graph replay
    }
    g_off[NE] = s;
}
__global__ void k_scatter(const int* __restrict__ z, int T) {
    __shared__ int h[NE], base[NE];
    if (threadIdx.x < NE) h[threadIdx.x] = 0;
    __syncthreads();
    int i = blockIdx.x * blockDim.x + threadIdx.x;
    int e = -1;
    if (i < T) {
        e = z[i];
        atomicAdd(&h[e], 1);
    }
    __syncthreads();
    if (threadIdx.x < NE) {
        base[threadIdx.x] = atomicAdd(&g_cur[threadIdx.x], h[threadIdx.x]);
        h[threadIdx.x] = 0;
    }
    __syncthreads();
    if (i < T) {
        int r = atomicAdd(&h[e], 1);
        g_idx[base[e] + r] = i;
    }
}

// ---- one-time W conversion into swizzled SMEM tile images ------------------
// block = (expert, chunk). Output per (e,c,nh): 32KB = [hi 16KB][lo 16KB],
// SW64-swizzled [n=256][k=32] bf16, ready for one bulk copy.
__global__ void k_convW(const float* __restrict__ W) {
    int blk = blockIdx.x;
    int e = blk >> 4;
    int c = blk & 15;
    int k0 = c * BK;
    int tid = threadIdx.x;
    int kq = tid >> 6;              // 0..3 -> k rows kq*8..+8
    int nq = tid & 63;              // n groups of 8
    const float* Wb = W + (size_t)e * D * D;
#pragma unroll
    for (int nn = 0; nn < 8; nn++) {
        int n = nq * 8 + nn;
        int nh = n >> 8;
        int nl = n & 255;
        float w[8];
#pragma unroll
        for (int kk = 0; kk < 8; kk++)
            w[kk] = Wb[(size_t)(k0 + kq * 8 + kk) * D + n];
        uint32_t hv[4], lv[4];
#pragma unroll
        for (int kp = 0; kp < 4; kp++)
            split2(w[2 * kp], w[2 * kp + 1], hv[kp], lv[kp]);
        unsigned char* base = g_Wimg + ((size_t)blk * 2 + nh) * 32768;
        uint32_t off = SWZ64((uint32_t)(nl * 64 + kq * 16));
        *(uint4*)(base + off) = make_uint4(hv[0], hv[1], hv[2], hv[3]);
        *(uint4*)(base + 16384 + off) = make_uint4(lv[0], lv[1], lv[2], lv[3]);
    }
}

// -- tcgen05 grouped GEMM: occ-2, in-loop A, dedicated B-producer warp -------
// Pair-adjacent nh mapping: tile = blockIdx.x >> 1, nh = blockIdx.x & 1, so
// the two CTAs gathering the same token rows run temporally adjacent and the
// second x gather hits L2 instead of DRAM.
__global__ __launch_bounds__(NTH, 2)
void k_gemm_tc(const float* __restrict__ x, const float* __restrict__ bias_g,
               float* __restrict__ y) {
#if TC_OK
    extern __shared__ char smem[];
    const uint32_t sb = smem_u32(smem);
    float* bias_s = (float*)(smem + SM_BIAS);
    int* tok_s = (int*)(smem + SM_TOK);

    // ---- map blockIdx.x -> (tile, nh) -> (expert, row offset) ----
    int tile = blockIdx.x >> 1;
    const int nh = blockIdx.x & 1;        // N-half 0/1
    int e = -1, m0 = 0, cnt = 0;
    {
        int t0 = 0;
#pragma unroll
        for (int q = 0; q < NE; q++) {
            int c = g_off[q + 1] - g_off[q];
            int nt = (c + BM - 1) / BM;
            if (e < 0 && tile < t0 + nt) {
                e = q;
                m0 = (tile - t0) * BM;
                cnt = c;
            }
            t0 += nt;
        }
    }
    if (e < 0) return;
    const int seg = g_off[e];
    const int n0 = nh * BN;

    const int tid = threadIdx.x;
    const int wid = tid >> 5;
    const int lane = tid & 31;

    if (tid < BN) bias_s[tid] = bias_g[(size_t)e * D + n0 + tid];
    if (tid < BM) {
        int r = m0 + tid;
        tok_s[tid] = (r < cnt) ? g_idx[seg + r] : -1;
    }
    if (wid == 0) {
        tmem_alloc(sb + SM_TP, 256);
        tmem_relinquish();
    }
    if (tid == 0) {
        mbar_init(sb + SM_MBE0, 1);
        mbar_init(sb + SM_MBE1, 1);
        mbar_init(sb + SM_MBF0, 1);
        mbar_init(sb + SM_MBF1, 1);
    }
    __syncthreads();
    uint32_t tmem;
    asm volatile("ld.shared.b32 %0, [%1];" : "=r"(tmem) : "r"(sb + SM_TP));

    const unsigned char* wsrc0 =
        g_Wimg + ((size_t)e * NCHUNK * 2 + nh) * 32768;

    if (wid == 16) {
        // ------- dedicated B producer: runs up to 2 chunks ahead ------------
        if (elect_one()) {
            for (int c = 0; c < NCHUNK; c++) {
                const int s = c & 1;
                if (c >= 2)
                    mbar_wait(sb + (s ? SM_MBE1 : SM_MBE0),
                              ((c >> 1) & 1) ^ 1);
                const uint32_t mbF = sb + (s ? SM_MBF1 : SM_MBF0);
                mbar_arrive_tx(mbF, 32768);
                bulk_g2s(sb + SM_B + s * 32768, wsrc0 + (size_t)c * 65536,
                         32768, mbF);
            }
        }
    } else {
        // ------- compute warps 0-15: A conversion + MMA issue ---------------
        const int row0 = tid >> 3;
        const int row1 = (tid + 512) >> 3;
        const int c4 = tid & 7;
        const int tk0 = tok_s[row0];
        const int tk1 = tok_s[row1];
        const float* p0 = (tk0 >= 0) ? x + (size_t)tk0 * D + c4 * 4 : 0;
        const float* p1 = (tk1 >= 0) ? x + (size_t)tk1 * D + c4 * 4 : 0;
        const uint32_t offA0 = SWZ64((uint32_t)(row0 * 64 + c4 * 8));
        const uint32_t offA1 = SWZ64((uint32_t)(row1 * 64 + c4 * 8));

        float4 v0, v1;
        const float4 fz = make_float4(0.f, 0.f, 0.f, 0.f);
        v0 = p0 ? *(const float4*)(p0) : fz;
        v1 = p1 ? *(const float4*)(p1) : fz;

        for (int c = 0; c < NCHUNK; c++) {
            const int s = c & 1;
            const uint32_t phase = (uint32_t)((c >> 1) & 1);
            const uint32_t mbE = sb + (s ? SM_MBE1 : SM_MBE0);
            const uint32_t mbF = sb + (s ? SM_MBF1 : SM_MBF0);

            // stage reuse: wait for MMAs of chunk c-2 (same stage)
            if (c >= 2) mbar_wait(mbE, phase ^ 1);

            // A: split prefetched regs -> hi/lo bf16, SW64
            char* Ah = smem + SM_A + s * 16384;
            char* Al = Ah + 8192;
            {
                uint32_t h0, l0, h1, l1;
                split2(v0.x, v0.y, h0, l0);
                split2(v0.z, v0.w, h1, l1);
                *(uint2*)(Ah + offA0) = make_uint2(h0, h1);
                *(uint2*)(Al + offA0) = make_uint2(l0, l1);
                split2(v1.x, v1.y, h0, l0);
                split2(v1.z, v1.w, h1, l1);
                *(uint2*)(Ah + offA1) = make_uint2(h0, h1);
                *(uint2*)(Al + offA1) = make_uint2(l0, l1);
            }

            // prefetch next chunk's A (issues before any blocking)
            if (c + 1 < NCHUNK) {
                int k0n = (c + 1) * BK;
                v0 = p0 ? *(const float4*)(p0 + k0n) : fz;
                v1 = p1 ? *(const float4*)(p1 + k0n) : fz;
            }

            fence_async_smem();
            // full named barrier over the 512 compute threads
            asm volatile("bar.sync 1, 512;" ::: "memory");

            if (wid == 0) {
                if (elect_one()) {
                    mbar_wait(mbF, phase);       // B landed (pre-issued)
                    uint64_t aH = sw64_desc(sb + SM_A + s * 16384);
                    uint64_t aL = aH + 512;      // +8192B in 16B units
                    uint64_t bH = sw64_desc(sb + SM_B + s * 32768);
                    uint64_t bL = bH + 1024;     // +16384B
#pragma unroll
                    for (int ks = 0; ks < 2; ks++) {
                        uint64_t dk = ks * 2;    // +32B per K=16 step
                        uint32_t first = (c == 0 && ks == 0) ? 0u : 1u;
                        mma_f16_ss(tmem, aH + dk, bH + dk, IDESC, first);
                        mma_f16_ss(tmem, aH + dk, bL + dk, IDESC, 1u);
                        mma_f16_ss(tmem, aL + dk, bH + dk, IDESC, 1u);
                    }
                    tc_commit(mbE);
                }
            }
        }

        // ---- drain: last completions are parity 1 on both stages ----
        mbar_wait(sb + SM_MBE0, 1);
        mbar_wait(sb + SM_MBE1, 1);
        tc_fence_after();

        // ---- epilogue: 16 warps, each 32 rows x 64 cols ----
        const int g = wid & 3;                // row group
        const int h = wid >> 2;               // col quarter (0..3)
        const int row = g * 32 + lane;
        const int tk = tok_s[row];
        const int cb = h * 64;
        const uint32_t dbase = tmem + cb;
        float* dst = (tk >= 0) ? (y + (size_t)tk * D + n0 + cb) : 0;

#pragma unroll
        for (int i = 0; i < 2; i++) {
            uint32_t r[32];
            ldtm_x32(r, dbase + i * 32);
            tmem_wait_ld();
            if (tk >= 0) {
#pragma unroll
                for (int cc = 0; cc < 32; cc += 4) {
                    float4 o;
                    o.x = __uint_as_float(r[cc + 0]) + bias_s[cb + i * 32 + cc + 0];
                    o.y = __uint_as_float(r[cc + 1]) + bias_s[cb + i * 32 + cc + 1];
                    o.z = __uint_as_float(r[cc + 2]) + bias_s[cb + i * 32 + cc + 2];
                    o.w = __uint_as_float(r[cc + 3]) + bias_s[cb + i * 32 + cc + 3];
                    *(float4*)(dst + i * 32 + cc) = o;
                }
            }
        }
    }

    __syncthreads();                          // all 17 warps re-join
    if (wid == 0) tmem_dealloc(tmem, 256);
#endif // TC_OK
}

// ---------------- fallback fp32 f32x2 GEMM (empty stub when TC_OK) ----------
#define FBM 128
#define FBN 128
#define FBK 16
#define FPAD 4

__global__ __launch_bounds__(256, 2)
void k_gemm_fb(const float* __restrict__ x, const float* __restrict__ W,
               const float* __restrict__ bias_g, float* __restrict__ y) {
#if !TC_OK
    __shared__ float As[FBK][FBM + FPAD];
    __shared__ float Bs[FBK][FBN + FPAD];
    __shared__ int tok[FBM];

    int tile = blockIdx.x;
    int e = -1, m0 = 0, cnt = 0;
    {
        int t0 = 0;
#pragma unroll
        for (int q = 0; q < NE; q++) {
            int c = g_off[q + 1] - g_off[q];
            int nt = (c + FBM - 1) / FBM;
            if (e < 0 && tile < t0 + nt) {
                e = q;
                m0 = (tile - t0) * FBM;
                cnt = c;
            }
            t0 += nt;
        }
    }
    if (e < 0) return;
    int seg = g_off[e];
    int n0 = blockIdx.y * FBN;

    int t = threadIdx.x;
    int ty = t >> 4;
    int tx = t & 15;

    if (t < FBM) {
        int r = m0 + t;
        tok[t] = (r < cnt) ? g_idx[seg + r] : -1;
    }
    __syncthreads();

    const float* Wbase = W + (size_t)e * D * D;

    unsigned long long acc[8][4];
#pragma unroll
    for (int i = 0; i < 8; i++)
#pragma unroll
        for (int j = 0; j < 4; j++) acc[i][j] = 0ULL;

    for (int kt = 0; kt < D / FBK; kt++) {
        int k0 = kt * FBK;
#pragma unroll
        for (int l = 0; l < 2; l++) {
            int i = t + l * 256;
            int row = i >> 2;
            int c4 = i & 3;
            int tk = tok[row];
            float4 v = make_float4(0.f, 0.f, 0.f, 0.f);
            if (tk >= 0)
                v = *(const float4*)(x + (size_t)tk * D + k0 + c4 * 4);
            As[c4 * 4 + 0][row] = v.x;
            As[c4 * 4 + 1][row] = v.y;
            As[c4 * 4 + 2][row] = v.z;
            As[c4 * 4 + 3][row] = v.w;
        }
#pragma unroll
        for (int l = 0; l < 2; l++) {
            int i = t + l * 256;
            int row = i >> 5;
            int c4 = i & 31;
            float4 v = *(const float4*)(Wbase + (size_t)(k0 + row) * D + n0 + c4 * 4);
            *(float4*)&Bs[row][c4 * 4] = v;
        }
        __syncthreads();

#pragma unroll
        for (int k = 0; k < FBK; k++) {
            float a[8], bb[8];
            {
                float4 a0 = *(const float4*)&As[k][ty * 4];
                float4 a1 = *(const float4*)&As[k][64 + ty * 4];
                a[0] = a0.x; a[1] = a0.y; a[2] = a0.z; a[3] = a0.w;
                a[4] = a1.x; a[5] = a1.y; a[6] = a1.z; a[7] = a1.w;
                float4 b0 = *(const float4*)&Bs[k][tx * 4];
                float4 b1 = *(const float4*)&Bs[k][64 + tx * 4];
                bb[0] = b0.x; bb[1] = b0.y; bb[2] = b0.z; bb[3] = b0.w;
                bb[4] = b1.x; bb[5] = b1.y; bb[6] = b1.z; bb[7] = b1.w;
            }
            unsigned long long b2[4];
#pragma unroll
            for (int j = 0; j < 4; j++) {
                asm("mov.b64 %0, {%1, %2};"
                    : "=l"(b2[j])
                    : "r"(__float_as_uint(bb[2 * j])),
                      "r"(__float_as_uint(bb[2 * j + 1])));
            }
#pragma unroll
            for (int i = 0; i < 8; i++) {
                unsigned long long a2;
                asm("mov.b64 %0, {%1, %1};"
                    : "=l"(a2)
                    : "r"(__float_as_uint(a[i])));
#pragma unroll
                for (int j = 0; j < 4; j++) {
                    asm("fma.rn.f32x2 %0, %1, %2, %0;"
                        : "+l"(acc[i][j])
                        : "l"(a2), "l"(b2[j]));
                }
            }
        }
        __syncthreads();
    }

    float bv[8];
    {
        float4 q0 = *(const float4*)(bias_g + (size_t)e * D + n0 + tx * 4);
        float4 q1 = *(const float4*)(bias_g + (size_t)e * D + n0 + 64 + tx * 4);
        bv[0] = q0.x; bv[1] = q0.y; bv[2] = q0.z; bv[3] = q0.w;
        bv[4] = q1.x; bv[5] = q1.y; bv[6] = q1.z; bv[7] = q1.w;
    }
#pragma unroll
    for (int i = 0; i < 8; i++) {
        int row = (i < 4) ? (ty * 4 + i) : (64 + ty * 4 + (i - 4));
        int tk = tok[row];
        if (tk < 0) continue;
        float o[8];
#pragma unroll
        for (int j = 0; j < 4; j++) {
            unsigned r0, r1;
            asm("mov.b64 {%0, %1}, %2;"
                : "=r"(r0), "=r"(r1)
                : "l"(acc[i][j]));
            o[2 * j] = __uint_as_float(r0) + bv[2 * j];
            o[2 * j + 1] = __uint_as_float(r1) + bv[2 * j + 1];
        }
        float* dst = y + (size_t)tk * D + n0;
        *(float4*)(dst + tx * 4) = make_float4(o[0], o[1], o[2], o[3]);
        *(float4*)(dst + 64 + tx * 4) = make_float4(o[4], o[5], o[6], o[7]);
    }
#endif // !TC_OK
}

// ---------------------------------------------------------------------------
extern "C" void kernel_launch(void* const* d_in, const int* in_sizes, int n_in,
                              void* d_out, int out_size) {
    const int* z = (const int*)d_in[0];
    const float* x = (const float*)d_in[1];
    const float* W = (const float*)d_in[2];
    const float* b = (const float*)d_in[3];
    float* out = (float*)d_out;

    int T = in_sizes[0];
    if (T > MAXT) T = MAXT;
    long long y_elems = (long long)T * D;
    long long prefix = (long long)out_size - y_elems;
    if (prefix < 0) prefix = 0;
    float* y = out + prefix;

    k_count<<<256, 256>>>(z, T, out, (prefix >= T) ? 1 : 0);
    k_scan<<<1, 1>>>();
    k_scatter<<<(T + 255) / 256, 256>>>(z, T);
    k_convW<<<NE * NCHUNK, 256>>>(W);

    // tcgen05 path (no-op stub if this cubin lacks the 'a' feature set)
    cudaFuncSetAttribute(k_gemm_tc, cudaFuncAttributeMaxDynamicSharedMemorySize,
                         SM_TOTAL);
    int ntiles = (T + BM - 1) / BM + NE;
    k_gemm_tc<<<2 * ntiles, NTH, SM_TOTAL>>>(x, b, y);

    // fp32 fallback (no-op stub when the tcgen05 path is compiled in)
    dim3 grid_fb((T + FBM - 1) / FBM + NE, D / FBN);
    k_gemm_fb<<<grid_fb, 256>>>(x, W, b, y);
}